// round 14
// baseline (speedup 1.0000x reference)
#include <cuda_runtime.h>
#include <stdint.h>
#include <math.h>

#define HID 1024
#define NE 64
#define MAXBS 1024
#define EPCAP 1024
#define TB 16            // tokens per phaseB chunk
#define KCB 64           // hidden-dim per pipeline stage
#define NCI (HID / KCB)  // 16 stages per chunk
#define NSTG 4           // pipeline depth (lookahead = 2 stages)

// phaseB dynamic smem layout (bytes)
#define WS_BYTES (NSTG * 64 * 17 * 16)          // 69632
#define XS_BYTES (NSTG * TB * 17 * 16)          // 17408
#define RES_BYTES (TB * 65 * 4)                 // 4160
#define TL_BYTES (EPCAP * 4)                    // 4096
#define SMEM_B (WS_BYTES + XS_BYTES + RES_BYTES + TL_BYTES)

// phaseA dynamic smem layout (bytes)
#define WSA_BYTES (NSTG * 64 * 17 * 16)         // 69632
#define XSA_BYTES (NSTG * 8 * 17 * 16)          // 8704
#define LG_BYTES  (8 * 64 * 4)                  // 2048
#define SMEM_A (WSA_BYTES + XSA_BYTES + LG_BYTES)

// ---- device scratch (allocation-free) ----
__device__ int g_slotexp[MAXBS * 4];  // [token*4+slot] -> expert id
__device__ int g_prog[MAXBS];         // completion counter per token
__device__ int g_ids[MAXBS * 12];     // per-token candidate ids (masked = -10000)

__device__ __forceinline__ void cp16(unsigned int dst, const void* src) {
    asm volatile("cp.async.cg.shared.global [%0], [%1], 16;" :: "r"(dst), "l"(src));
}
__device__ __forceinline__ void cp16p(unsigned int dst, const void* src, int valid) {
    asm volatile("cp.async.cg.shared.global [%0], [%1], 16, %2;"
                 :: "r"(dst), "l"(src), "r"(valid ? 16 : 0));
}
__device__ __forceinline__ void cp_commit() { asm volatile("cp.async.commit_group;"); }
__device__ __forceinline__ void cp_wait2() { asm volatile("cp.async.wait_group 2;"); }
__device__ __forceinline__ unsigned int smem_u32(const void* p) {
    return (unsigned int)__cvta_generic_to_shared(p);
}
// packed f32x2 fma: acc += a * b (elementwise on 2 packed floats)
__device__ __forceinline__ void fma2(unsigned long long& acc,
                                     unsigned long long a, unsigned long long b) {
    asm("fma.rn.f32x2 %0, %1, %2, %0;" : "+l"(acc) : "l"(a), "l"(b));
}
__device__ __forceinline__ float unpack_sum(unsigned long long lo, unsigned long long hi) {
    float s0, s1, s2, s3;
    asm("mov.b64 {%0,%1}, %2;" : "=f"(s0), "=f"(s1) : "l"(lo));
    asm("mov.b64 {%0,%1}, %2;" : "=f"(s2), "=f"(s3) : "l"(hi));
    return (s0 + s1) + (s2 + s3);
}

// ============================================================
// Phase A: router GEMM (8 tokens/block) with 4-stage cp.async
// pipeline + packed f32x2 FMA; top-4 + renorm weights; writes
// final_weights, slot->expert map, zeroes g_prog.
// ============================================================
__global__ __launch_bounds__(256) void phaseA(const float* __restrict__ x,
                                              const float* __restrict__ wg,
                                              float* __restrict__ outw,
                                              int bs) {
    extern __shared__ char dsa[];
    float4     (*ws4)[64][17] = reinterpret_cast<float4(*)[64][17]>(dsa);
    ulonglong2 (*wsU)[64][17] = reinterpret_cast<ulonglong2(*)[64][17]>(dsa);
    float4     (*xs4)[8][17]  = reinterpret_cast<float4(*)[8][17]>(dsa + WSA_BYTES);
    ulonglong2 (*xsU)[8][17]  = reinterpret_cast<ulonglong2(*)[8][17]>(dsa + WSA_BYTES);
    float      (*lg)[64]      = reinterpret_cast<float(*)[64]>(dsa + WSA_BYTES + XSA_BYTES);

    int t  = threadIdx.x;
    int r  = t & 63;
    int tg = t >> 6;
    int tok0 = blockIdx.x * 8;

    int wrow = t >> 4;
    int wcol = t & 15;
    int xtok = tok0 + wrow - 8;
    int do_x = (wrow >= 8) && (wrow < 16);
    const float4* xsrcA = reinterpret_cast<const float4*>(x) +
        ((do_x && xtok < bs) ? (size_t)xtok * (HID / 4) : 0);
    int xvalid = do_x && (xtok < bs);

    #pragma unroll
    for (int s = 0; s < NSTG - 1; ++s) {
        int gc = s * 16 + wcol;
        #pragma unroll
        for (int i = 0; i < 4; ++i)
            cp16(smem_u32(&ws4[s][wrow + 16 * i][wcol]),
                 reinterpret_cast<const float4*>(wg) + (size_t)(wrow + 16 * i) * (HID / 4) + gc);
        if (do_x)
            cp16p(smem_u32(&xs4[s][wrow - 8][wcol]), xsrcA + gc, xvalid);
        cp_commit();
    }

    unsigned long long a0[2] = {0, 0}, a1[2] = {0, 0};
    #pragma unroll
    for (int c = 0; c < NCI; ++c) {
        int cb = c % NSTG;
        cp_wait2();
        __syncthreads();
        #pragma unroll
        for (int k = 0; k < 16; ++k) {
            ulonglong2 w = wsU[cb][r][k];
            ulonglong2 va = xsU[cb][tg][k];
            ulonglong2 vb = xsU[cb][tg + 4][k];
            fma2(a0[0], w.x, va.x); fma2(a0[1], w.y, va.y);
            fma2(a1[0], w.x, vb.x); fma2(a1[1], w.y, vb.y);
        }
        if (c + NSTG - 1 < NCI) {
            int nb = (c + NSTG - 1) % NSTG;
            int gc = (c + NSTG - 1) * 16 + wcol;
            #pragma unroll
            for (int i = 0; i < 4; ++i)
                cp16(smem_u32(&ws4[nb][wrow + 16 * i][wcol]),
                     reinterpret_cast<const float4*>(wg) + (size_t)(wrow + 16 * i) * (HID / 4) + gc);
            if (do_x)
                cp16p(smem_u32(&xs4[nb][wrow - 8][wcol]), xsrcA + gc, xvalid);
        }
        cp_commit();
    }
    lg[tg][r]     = unpack_sum(a0[0], a0[1]);
    lg[tg + 4][r] = unpack_sum(a1[0], a1[1]);
    __syncthreads();

    if (t < 8) {
        int token = tok0 + t;
        if (token < bs) {
            g_prog[token] = 0;
            unsigned long long used = 0ULL;
            int sel[4]; float lv[4];
            #pragma unroll
            for (int s = 0; s < 4; ++s) {
                float best = -INFINITY; int bi = 0;
                for (int e = 0; e < NE; ++e) {
                    if ((used >> e) & 1ULL) continue;
                    float v = lg[t][e];
                    if (v > best) { best = v; bi = e; }
                }
                used |= 1ULL << bi;
                sel[s] = bi; lv[s] = best;
            }
            float m  = lv[0];
            float w0 = 1.f;
            float w1 = expf(lv[1] - m);
            float w2 = expf(lv[2] - m);
            float w3 = expf(lv[3] - m);
            float z  = w0 + w1 + w2 + w3;
            w0 /= z; w1 /= z; w2 /= z; w3 /= z;
            float* o = outw + token * 8;
            o[0] = w0; o[1] = w0; o[2] = w0;
            o[3] = w1; o[4] = w1;
            o[5] = w2; o[6] = w2;
            o[7] = w3;
            #pragma unroll
            for (int s = 0; s < 4; ++s)
                g_slotexp[token * 4 + s] = sel[s];
        }
    }
}

// ============================================================
// Phase B: per-expert scan+group, 16-token chunks, 4-stage
// cp.async pipeline, conflict-free 4-row x 1-token lane tile
// with packed f32x2 FMA, silu scores, top-3, fused finalize.
// ============================================================
__global__ __launch_bounds__(256) void phaseB(const float* __restrict__ x,
                                              const float* __restrict__ gw,
                                              const float* __restrict__ uw,
                                              float* __restrict__ out,
                                              int bs) {
    extern __shared__ char dsm[];
    float4     (*ws4)[64][17] = reinterpret_cast<float4(*)[64][17]>(dsm);
    ulonglong2 (*wsU)[64][17] = reinterpret_cast<ulonglong2(*)[64][17]>(dsm);
    float4     (*xs4)[TB][17] = reinterpret_cast<float4(*)[TB][17]>(dsm + WS_BYTES);
    ulonglong2 (*xsU)[TB][17] = reinterpret_cast<ulonglong2(*)[TB][17]>(dsm + WS_BYTES);
    float      (*res)[65]     = reinterpret_cast<float(*)[65]>(dsm + WS_BYTES + XS_BYTES);
    int*       toklist        = reinterpret_cast<int*>(dsm + WS_BYTES + XS_BYTES + RES_BYTES);

    __shared__ int s_wsum[8], s_wbase[8], s_cnt;

    int e    = blockIdx.x;
    int t    = threadIdx.x;
    int lane = t & 31;
    int wid  = t >> 5;
    // compute-tile mapping: warp = (row-half, token-group); lane = (row, tok)
    int hb   = (wid & 1) * 32;       // row half base: 0 or 32
    int gb   = (wid >> 1) * 4;       // token group base: 0,4,8,12
    int rr   = lane >> 2;            // row-within-half 0..7 (rows hb+rr+8i)
    int tt   = lane & 3;             // token offset 0..3 (token gb+tt)

    // ---- deterministic scan of slot->expert map ----
    int flatN = bs * 4;
    int base_i = t * 16;
    int vals[16];
    #pragma unroll
    for (int i = 0; i < 16; i += 4) {
        int4 v4 = make_int4(-1, -1, -1, -1);
        if (base_i + i + 3 < flatN)
            v4 = reinterpret_cast<const int4*>(g_slotexp)[(base_i + i) >> 2];
        vals[i] = v4.x; vals[i + 1] = v4.y; vals[i + 2] = v4.z; vals[i + 3] = v4.w;
    }
    int cl = 0;
    #pragma unroll
    for (int i = 0; i < 16; ++i) cl += (vals[i] == e);
    int pre = cl;
    #pragma unroll
    for (int o = 1; o < 32; o <<= 1) {
        int v = __shfl_up_sync(0xFFFFFFFFu, pre, o);
        if (lane >= o) pre += v;
    }
    if (lane == 31) s_wsum[wid] = pre;
    __syncthreads();
    if (t == 0) {
        int run = 0;
        #pragma unroll
        for (int w = 0; w < 8; ++w) { s_wbase[w] = run; run += s_wsum[w]; }
        s_cnt = run;
    }
    __syncthreads();
    int p = s_wbase[wid] + pre - cl;
    #pragma unroll
    for (int i = 0; i < 16; ++i) {
        if (vals[i] == e && p < EPCAP) toklist[p++] = base_i + i;
    }
    __syncthreads();
    int cnt = s_cnt < EPCAP ? s_cnt : EPCAP;

    // staging maps: 256 threads -> 16 rows x 16 cols
    int wrow = t >> 4;
    int wcol = t & 15;
    const float4* wsrc[4];
    #pragma unroll
    for (int i = 0; i < 4; ++i) {
        int row = wrow + 16 * i;
        const float* s = (row < 32) ? gw + ((size_t)e * 32 + row) * HID
                                    : uw + ((size_t)e * 32 + (row - 32)) * HID;
        wsrc[i] = reinterpret_cast<const float4*>(s);
    }

    for (int chunk = blockIdx.y; chunk * TB < cnt; chunk += gridDim.y) {
        int base = chunk * TB;
        int prx = (base + wrow < cnt) ? toklist[base + wrow] : -1;
        const float4* xsrc = reinterpret_cast<const float4*>(x) +
                             (prx >= 0 ? (size_t)(prx >> 2) * (HID / 4) : 0);

        // prologue: issue stages 0..2
        #pragma unroll
        for (int s = 0; s < NSTG - 1; ++s) {
            int gc = s * 16 + wcol;
            #pragma unroll
            for (int i = 0; i < 4; ++i)
                cp16(smem_u32(&ws4[s][wrow + 16 * i][wcol]), wsrc[i] + gc);
            cp16p(smem_u32(&xs4[s][wrow][wcol]), xsrc + gc, prx >= 0);
            cp_commit();
        }

        // packed accumulators: [row i][lo/hi], rows hb+rr+8i, token gb+tt
        unsigned long long a[4][2] = {{0,0},{0,0},{0,0},{0,0}};

        #pragma unroll
        for (int c = 0; c < NCI; ++c) {
            int cb = c % NSTG;
            cp_wait2();                      // stage c done; c+1,c+2 in flight
            __syncthreads();
            #pragma unroll
            for (int k = 0; k < 16; ++k) {
                ulonglong2 xv = xsU[cb][gb + tt][k];   // 4-distinct, 1 phase
                #pragma unroll
                for (int i = 0; i < 4; ++i) {
                    ulonglong2 wv = wsU[cb][hb + rr + 8 * i][k];  // 8-distinct, 1 phase
                    fma2(a[i][0], wv.x, xv.x);
                    fma2(a[i][1], wv.y, xv.y);
                }
            }
            if (c + NSTG - 1 < NCI) {        // issue stage c+3 into buf (c+3)%4
                int nb = (c + NSTG - 1) % NSTG;
                int gc = (c + NSTG - 1) * 16 + wcol;
                #pragma unroll
                for (int i = 0; i < 4; ++i)
                    cp16(smem_u32(&ws4[nb][wrow + 16 * i][wcol]), wsrc[i] + gc);
                cp16p(smem_u32(&xs4[nb][wrow][wcol]), xsrc + gc, prx >= 0);
            }
            cp_commit();                     // keep group counts aligned
        }
        #pragma unroll
        for (int i = 0; i < 4; ++i)
            res[gb + tt][hb + rr + 8 * i] = unpack_sum(a[i][0], a[i][1]);
        __syncthreads();

        // ---- scoring + inner top-3 + fused finalize ----
        if (t < TB) {
            int pr = (base + t < cnt) ? toklist[base + t] : -1;
            if (pr >= 0) {
                int token = pr >> 2;
                int slot  = pr & 3;
                float inner[8];
                #pragma unroll
                for (int i = 0; i < 8; ++i) {
                    float s = 0.f;
                    #pragma unroll
                    for (int b = 0; b < 4; ++b) {
                        int j   = i * 4 + b;
                        float g = res[t][j];
                        float u = res[t][32 + j];
                        float sil = g / (1.f + expf(-g));
                        s += fabsf(u * sil);
                    }
                    inner[i] = s * 0.25f;
                }
                int keep = (slot == 0) ? 3 : ((slot == 3) ? 1 : 2);  // pattern (3,2,2,1)
                int outb = token * 12 + slot * 3;
                unsigned used = 0;
                #pragma unroll
                for (int jj = 0; jj < 3; ++jj) {
                    float best = -INFINITY; int bi = 0;
                    #pragma unroll
                    for (int i = 0; i < 8; ++i) {
                        if ((used >> i) & 1u) continue;
                        if (inner[i] > best) { best = inner[i]; bi = i; }
                    }
                    used |= 1u << bi;
                    g_ids[outb + jj] = (jj < keep) ? (e * 8 + bi) : -10000;
                }
                __threadfence();
                int done = atomicAdd(&g_prog[token], 1);
                if (done == 3) {
                    __threadfence();
                    int v[12];
                    #pragma unroll
                    for (int i = 0; i < 12; ++i) v[i] = g_ids[token * 12 + i];
                    #pragma unroll
                    for (int i = 1; i < 12; ++i) {
                        int key = v[i], j2 = i - 1;
                        while (j2 >= 0 && v[j2] < key) { v[j2 + 1] = v[j2]; --j2; }
                        v[j2 + 1] = key;
                    }
                    #pragma unroll
                    for (int i = 0; i < 8; ++i)
                        out[token * 8 + i] = (float)v[i];
                }
            }
        }
        __syncthreads();   // protect buffers + toklist before next chunk
    }
}

extern "C" void kernel_launch(void* const* d_in, const int* in_sizes, int n_in,
                              void* d_out, int out_size) {
    const float* x  = (const float*)d_in[0];
    const float* wg = (const float*)d_in[1];
    const float* gw = (const float*)d_in[2];
    const float* uw = (const float*)d_in[3];
    float* out = (float*)d_out;

    int bs = in_sizes[0] / HID;
    if (bs > MAXBS) bs = MAXBS;

    cudaFuncSetAttribute(phaseA, cudaFuncAttributeMaxDynamicSharedMemorySize, SMEM_A);
    cudaFuncSetAttribute(phaseB, cudaFuncAttributeMaxDynamicSharedMemorySize, SMEM_B);

    phaseA<<<(bs + 7) / 8, 256, SMEM_A>>>(x, wg, out + bs * 8, bs);
    phaseB<<<dim3(NE, 6), 256, SMEM_B>>>(x, gw, uw, out, bs);
}